// round 5
// baseline (speedup 1.0000x reference)
#include <cuda_runtime.h>
#include <cuda_bf16.h>
#include <math.h>

// WarpTranspose: adjoint of bilinear warp (flow-guided bilinear scatter-add).
// grad_out: [B,H,W,C] f32, u: [B,H,W,2] f32 (dx,dy), out: [B,H,W,C] f32.
//
// Persistent co-resident kernel pipelines per-image zeroing with per-image
// scatter: all valid scatter targets stay inside the source image (corners
// outside [0,H)x[0,W) get zero weight), so scatter(img i) depends only on
// zero(img i). Block schedule: zero(i); flag(i); wait(i-1); scatter(i-1).
// With NB=592 blocks (4/SM @256thr, always co-resident) the spin-waits are
// deadlock-free: every block flags image m before waiting on m-1.

#define H_DIM 512
#define W_DIM 512
#define C_DIM 16
#define B_MAX 16
#define NB 592
#define NT (NB * 256)

__device__ int g_zcnt[B_MAX];

__global__ void reset_flags() {
    if (threadIdx.x < B_MAX) g_zcnt[threadIdx.x] = 0;
}

__device__ __forceinline__ void scatter_image(const float* __restrict__ grad_out,
                                              const float* __restrict__ u,
                                              float* __restrict__ out,
                                              int img, int t) {
    const int HW = H_DIM * W_DIM;
    const int quads = 4 * HW;
    const long long pix_base = (long long)img * HW;

    for (int q = t; q < quads; q += NT) {
        const int quad = q & 3;
        const int lp   = q >> 2;                 // pixel within image
        const long long p = pix_base + lp;

        const int x = lp & (W_DIM - 1);
        const int y = (lp >> 9) & (H_DIM - 1);

        const float2 uv = __ldg((const float2*)(u + 2 * p));
        const float gx = (float)x + uv.x;
        const float gy = (float)y + uv.y;

        const float x0f = floorf(gx);
        const float y0f = floorf(gy);
        const float wx = gx - x0f;
        const float wy = gy - y0f;
        const int x0 = (int)x0f;
        const int y0 = (int)y0f;
        const int x1 = x0 + 1;
        const int y1 = y0 + 1;

        const float4 g = __ldg((const float4*)(grad_out + p * C_DIM + quad * 4));

        const bool vx0 = ((unsigned)x0 < (unsigned)W_DIM);
        const bool vx1 = ((unsigned)x1 < (unsigned)W_DIM);
        const bool vy0 = ((unsigned)y0 < (unsigned)H_DIM);
        const bool vy1 = ((unsigned)y1 < (unsigned)H_DIM);

        const float w00 = (1.0f - wy) * (1.0f - wx);
        const float w01 = (1.0f - wy) * wx;
        const float w10 = wy * (1.0f - wx);
        const float w11 = wy * wx;

        const int dy0 = (y0 - y) * W_DIM;
        const int dy1 = dy0 + W_DIM;
        const int dx0 = x0 - x;
        float* outq = out + p * C_DIM + quad * 4;

        if (vy0 & vx0) {
            float4 v = make_float4(g.x * w00, g.y * w00, g.z * w00, g.w * w00);
            atomicAdd((float4*)(outq + (long long)(dy0 + dx0) * C_DIM), v);
        }
        if (vy0 & vx1) {
            float4 v = make_float4(g.x * w01, g.y * w01, g.z * w01, g.w * w01);
            atomicAdd((float4*)(outq + (long long)(dy0 + dx0 + 1) * C_DIM), v);
        }
        if (vy1 & vx0) {
            float4 v = make_float4(g.x * w10, g.y * w10, g.z * w10, g.w * w10);
            atomicAdd((float4*)(outq + (long long)(dy1 + dx0) * C_DIM), v);
        }
        if (vy1 & vx1) {
            float4 v = make_float4(g.x * w11, g.y * w11, g.z * w11, g.w * w11);
            atomicAdd((float4*)(outq + (long long)(dy1 + dx0 + 1) * C_DIM), v);
        }
    }
}

__global__ void __launch_bounds__(256)
warp_transpose_pipelined(const float* __restrict__ grad_out,
                         const float* __restrict__ u,
                         float* __restrict__ out,
                         int B) {
    const int t = blockIdx.x * 256 + threadIdx.x;
    const int f4_per_img = H_DIM * W_DIM * C_DIM / 4;   // float4 per image
    float4* out4 = (float4*)out;

    for (int img = 0; img < B; img++) {
        // ---- zero my share of image img (128-bit stores, coalesced) ----
        float4 z = make_float4(0.f, 0.f, 0.f, 0.f);
        const long long zb = (long long)img * f4_per_img;
        for (int k = t; k < f4_per_img; k += NT)
            out4[zb + k] = z;

        __threadfence();
        __syncthreads();
        if (threadIdx.x == 0) atomicAdd(&g_zcnt[img], 1);   // release flag

        // ---- scatter previous image (its zeroing is complete once all flag) --
        if (img > 0) {
            if (threadIdx.x == 0) {
                while (*((volatile int*)&g_zcnt[img - 1]) < NB) __nanosleep(64);
            }
            __syncthreads();
            __threadfence();                                // acquire
            scatter_image(grad_out, u, out, img - 1, t);
        }
    }

    // ---- last image ----
    if (threadIdx.x == 0) {
        while (*((volatile int*)&g_zcnt[B - 1]) < NB) __nanosleep(64);
    }
    __syncthreads();
    __threadfence();
    scatter_image(grad_out, u, out, B - 1, t);
}

extern "C" void kernel_launch(void* const* d_in, const int* in_sizes, int n_in,
                              void* d_out, int out_size) {
    const float* grad_out = (const float*)d_in[0];
    const float* u        = (const float*)d_in[1];
    float* out = (float*)d_out;

    const int B = in_sizes[1] / (H_DIM * W_DIM * 2);

    reset_flags<<<1, 32>>>();
    warp_transpose_pipelined<<<NB, 256>>>(grad_out, u, out, B);
}

// round 6
// speedup vs baseline: 1.1504x; 1.1504x over previous
#include <cuda_runtime.h>
#include <cuda_bf16.h>
#include <math.h>

// WarpTranspose: adjoint of bilinear warp (flow-guided bilinear scatter-add).
// grad_out: [B,H,W,C] f32, u: [B,H,W,2] f32 (dx,dy), out: [B,H,W,C] f32.
//
// Single fused launch. Blocks are laid out in blockIdx order as
//   [z0][z1][s0][z2][s1][z3][s2] ... [s_{B-2}][s_{B-1}]
// z_i = ZB blocks zeroing image i; s_i = SB blocks scattering image i
// (all valid scatter targets stay inside source image i, since out-of-image
// corners get zero weight). s_i spin-waits on a per-image counter released by
// z_i. Every wait is on strictly-lower-blockIdx work, and the HW work
// distributor dispatches blocks in increasing bid order, so progress is
// guaranteed. Zeroing (DRAM STG) overlaps scatter (L1/L2 atomic RMW).

#define H_DIM 512
#define W_DIM 512
#define C_DIM 16
#define B_MAX 32
#define ZB 256          // zero blocks per image
#define SB 4096         // scatter blocks per image (1M quads / 256 thr)

__device__ int g_zcnt[B_MAX];

__global__ void reset_flags() {
    if (threadIdx.x < B_MAX) g_zcnt[threadIdx.x] = 0;
}

__global__ void __launch_bounds__(256)
warp_transpose_fused(const float* __restrict__ grad_out,
                     const float* __restrict__ u,
                     float* __restrict__ out,
                     int B) {
    // ---- decode role from blockIdx ----
    int bid = blockIdx.x;
    int img = 0, sub = 0;
    bool is_zero = false;

    const int lead = (B < 2 ? B : 2) * ZB;   // z0 (and z1) up front
    if (bid < lead) {
        is_zero = true;
        img = bid / ZB;
        sub = bid % ZB;
    } else {
        int b = bid - lead;
        for (int i = 0; i < B; i++) {
            if (b < SB) { img = i; sub = b; is_zero = false; break; }
            b -= SB;
            if (i + 2 < B) {
                if (b < ZB) { img = i + 2; sub = b; is_zero = true; break; }
                b -= ZB;
            }
        }
    }

    if (is_zero) {
        // ---- zero slab: 4096 float4 per block, coalesced ----
        const int f4_per_img = H_DIM * W_DIM * C_DIM / 4;       // 1048576
        const int f4_per_blk = f4_per_img / ZB;                 // 4096
        float4* o4 = (float4*)out + (long long)img * f4_per_img
                                  + (long long)sub * f4_per_blk;
        const float4 z = make_float4(0.f, 0.f, 0.f, 0.f);
        #pragma unroll 4
        for (int k = threadIdx.x; k < f4_per_blk; k += 256)
            o4[k] = z;

        __threadfence();
        __syncthreads();
        if (threadIdx.x == 0) atomicAdd(&g_zcnt[img], 1);       // release
        return;
    }

    // ---- scatter: wait until image is fully zeroed ----
    if (threadIdx.x == 0) {
        while (*((volatile int*)&g_zcnt[img]) < ZB) __nanosleep(32);
    }
    __syncthreads();
    __threadfence();                                            // acquire

    const int q    = sub * 256 + threadIdx.x;   // quad within image
    const int quad = q & 3;
    const int lp   = q >> 2;                    // pixel within image
    const long long p = (long long)img * (H_DIM * W_DIM) + lp;

    const int x = lp & (W_DIM - 1);
    const int y = (lp >> 9) & (H_DIM - 1);

    const float2 uv = __ldg((const float2*)(u + 2 * p));
    const float gx = (float)x + uv.x;
    const float gy = (float)y + uv.y;

    const float x0f = floorf(gx);
    const float y0f = floorf(gy);
    const float wx = gx - x0f;
    const float wy = gy - y0f;
    const int x0 = (int)x0f;
    const int y0 = (int)y0f;

    const float4 g = __ldg((const float4*)(grad_out + p * C_DIM + quad * 4));

    const bool vx0 = ((unsigned)x0 < (unsigned)W_DIM);
    const bool vx1 = ((unsigned)(x0 + 1) < (unsigned)W_DIM);
    const bool vy0 = ((unsigned)y0 < (unsigned)H_DIM);
    const bool vy1 = ((unsigned)(y0 + 1) < (unsigned)H_DIM);

    const float w00 = (1.0f - wy) * (1.0f - wx);
    const float w01 = (1.0f - wy) * wx;
    const float w10 = wy * (1.0f - wx);
    const float w11 = wy * wx;

    const int dy0 = (y0 - y) * W_DIM;
    const int dy1 = dy0 + W_DIM;
    const int dx0 = x0 - x;
    float* outq = out + p * C_DIM + quad * 4;

    if (vy0 & vx0) {
        float4 v = make_float4(g.x * w00, g.y * w00, g.z * w00, g.w * w00);
        atomicAdd((float4*)(outq + (long long)(dy0 + dx0) * C_DIM), v);
    }
    if (vy0 & vx1) {
        float4 v = make_float4(g.x * w01, g.y * w01, g.z * w01, g.w * w01);
        atomicAdd((float4*)(outq + (long long)(dy0 + dx0 + 1) * C_DIM), v);
    }
    if (vy1 & vx0) {
        float4 v = make_float4(g.x * w10, g.y * w10, g.z * w10, g.w * w10);
        atomicAdd((float4*)(outq + (long long)(dy1 + dx0) * C_DIM), v);
    }
    if (vy1 & vx1) {
        float4 v = make_float4(g.x * w11, g.y * w11, g.z * w11, g.w * w11);
        atomicAdd((float4*)(outq + (long long)(dy1 + dx0 + 1) * C_DIM), v);
    }
}

extern "C" void kernel_launch(void* const* d_in, const int* in_sizes, int n_in,
                              void* d_out, int out_size) {
    const float* grad_out = (const float*)d_in[0];
    const float* u        = (const float*)d_in[1];
    float* out = (float*)d_out;

    const int B = in_sizes[1] / (H_DIM * W_DIM * 2);

    reset_flags<<<1, 32>>>();
    const int grid = B * (ZB + SB);
    warp_transpose_fused<<<grid, 256>>>(grad_out, u, out, B);
}

// round 7
// speedup vs baseline: 1.5510x; 1.3482x over previous
#include <cuda_runtime.h>
#include <cuda_bf16.h>
#include <math.h>

// WarpTranspose: adjoint of bilinear warp (flow-guided bilinear scatter-add).
// grad_out: [B,H,W,C] f32, u: [B,H,W,2] f32 (dx,dy), out: [B,H,W,C] f32.
//
// R1 mapping (best known): 4 threads per pixel, one float4 channel-quad each,
// 4 x 64B-aligned float4 atomicAdds per pixel (64B regions never straddle a
// 128B line). This round: each thread processes TWO pixels (p, p + half) with
// all global loads front-batched for MLP, halving per-pixel overhead. Atomic
// sector count (the measured floor) is unchanged; this targets issue
// efficiency only. Zeroing stays a serial cudaMemsetAsync: measured on this
// chip, concurrent streaming zero-writes slow the atomic RMW path by more
// than the memset costs.

#define H_DIM 512
#define W_DIM 512
#define C_DIM 16

__device__ __forceinline__ void scatter_one(const float4 g, const float2 uv,
                                            int lp, int quad,
                                            float* __restrict__ outq_base) {
    const int x = lp & (W_DIM - 1);
    const int y = (lp >> 9) & (H_DIM - 1);

    const float gx = (float)x + uv.x;
    const float gy = (float)y + uv.y;

    const float x0f = floorf(gx);
    const float y0f = floorf(gy);
    const float wx = gx - x0f;
    const float wy = gy - y0f;
    const int x0 = (int)x0f;
    const int y0 = (int)y0f;

    const bool vx0 = ((unsigned)x0 < (unsigned)W_DIM);
    const bool vx1 = ((unsigned)(x0 + 1) < (unsigned)W_DIM);
    const bool vy0 = ((unsigned)y0 < (unsigned)H_DIM);
    const bool vy1 = ((unsigned)(y0 + 1) < (unsigned)H_DIM);

    const float w00 = (1.0f - wy) * (1.0f - wx);
    const float w01 = (1.0f - wy) * wx;
    const float w10 = wy * (1.0f - wx);
    const float w11 = wy * wx;

    const int dy0 = (y0 - y) * W_DIM;
    const int dy1 = dy0 + W_DIM;
    const int dx0 = x0 - x;

    if (vy0 & vx0) {
        float4 v = make_float4(g.x * w00, g.y * w00, g.z * w00, g.w * w00);
        atomicAdd((float4*)(outq_base + (dy0 + dx0) * C_DIM), v);
    }
    if (vy0 & vx1) {
        float4 v = make_float4(g.x * w01, g.y * w01, g.z * w01, g.w * w01);
        atomicAdd((float4*)(outq_base + (dy0 + dx0 + 1) * C_DIM), v);
    }
    if (vy1 & vx0) {
        float4 v = make_float4(g.x * w10, g.y * w10, g.z * w10, g.w * w10);
        atomicAdd((float4*)(outq_base + (dy1 + dx0) * C_DIM), v);
    }
    if (vy1 & vx1) {
        float4 v = make_float4(g.x * w11, g.y * w11, g.z * w11, g.w * w11);
        atomicAdd((float4*)(outq_base + (dy1 + dx0 + 1) * C_DIM), v);
    }
}

__global__ void __launch_bounds__(256)
warp_transpose_scatter(const float* __restrict__ grad_out,
                       const float* __restrict__ u,
                       float* __restrict__ out,
                       int half_quads) {
    const int gid = blockIdx.x * 256 + threadIdx.x;
    if (gid >= half_quads) return;

    // --- pixel A ---
    const int qA    = gid;
    const int quadA = qA & 3;
    const int lpA   = qA >> 2;
    // --- pixel B (second half of the tensor) ---
    const int qB    = gid + half_quads;
    const int quadB = qB & 3;
    const int lpB   = qB >> 2;

    // front-batched loads (MLP=4)
    const float2 uvA = __ldg((const float2*)(u + 2 * lpA));
    const float2 uvB = __ldg((const float2*)(u + 2 * lpB));
    const float4 gA  = __ldg((const float4*)(grad_out + lpA * C_DIM + quadA * 4));
    const float4 gB  = __ldg((const float4*)(grad_out + lpB * C_DIM + quadB * 4));

    // lpA/lpB encode (b*H + y)*W + x with per-image masks; relative offsets
    // from the source pixel stay inside the same batch image for all valid
    // (weight>0) corners, so 32-bit indexing off the source address is exact.
    scatter_one(gA, uvA, lpA & (H_DIM * W_DIM - 1), quadA,
                out + lpA * C_DIM + quadA * 4);
    scatter_one(gB, uvB, lpB & (H_DIM * W_DIM - 1), quadB,
                out + lpB * C_DIM + quadB * 4);
}

extern "C" void kernel_launch(void* const* d_in, const int* in_sizes, int n_in,
                              void* d_out, int out_size) {
    const float* grad_out = (const float*)d_in[0];
    const float* u        = (const float*)d_in[1];
    float* out = (float*)d_out;

    const int B = in_sizes[1] / (H_DIM * W_DIM * 2);
    const int total_quads = B * H_DIM * W_DIM * 4;
    const int half_quads = total_quads >> 1;

    // zero the (poisoned) output — legal graph node, no allocation
    cudaMemsetAsync(d_out, 0, (size_t)out_size * sizeof(float), 0);

    const int block = 256;
    const int grid = (half_quads + block - 1) / block;
    warp_transpose_scatter<<<grid, block>>>(grad_out, u, out, half_quads);
}

// round 8
// speedup vs baseline: 1.6333x; 1.0530x over previous
#include <cuda_runtime.h>
#include <cuda_bf16.h>
#include <math.h>

// WarpTranspose: adjoint of bilinear warp (flow-guided bilinear scatter-add).
// grad_out: [B,H,W,C] f32, u: [B,H,W,2] f32 (dx,dy), out: [B,H,W,C] f32.
//
// Structure: custom zero kernel (replaces slower in-graph memset) then the
// R1-shape scatter, which sits at the per-SM RED lane-op floor:
// 16 lane-ops/px (4 corners x 4 lanes RED.128) x 0.854 cyc/lane ~= 95-97us.

#define H_DIM 512
#define W_DIM 512
#define C_DIM 16

// ---------------- zero kernel: 134MB of float4 stores at DRAM speed --------
__global__ void __launch_bounds__(256)
zero_out(float4* __restrict__ out4, int n4) {
    const int stride = gridDim.x * 256;
    const float4 z = make_float4(0.f, 0.f, 0.f, 0.f);
    for (int i = blockIdx.x * 256 + threadIdx.x; i < n4; i += stride)
        out4[i] = z;
}

// ---------------- scatter: R1 mapping (best known, at RED floor) -----------
__global__ void __launch_bounds__(256)
warp_transpose_scatter(const float* __restrict__ grad_out,
                       const float* __restrict__ u,
                       float* __restrict__ out) {
    const int gid = blockIdx.x * 256 + threadIdx.x;   // grid is exact: no guard

    const int quad = gid & 3;      // which float4 of the 16 channels
    const int p    = gid >> 2;     // pixel index: ((b*H + y)*W + x)

    const int x = p & (W_DIM - 1);
    const int y = (p >> 9) & (H_DIM - 1);

    const float2 uv = __ldg((const float2*)(u + 2 * (size_t)p));
    const float gx = (float)x + uv.x;
    const float gy = (float)y + uv.y;

    const float x0f = floorf(gx);
    const float y0f = floorf(gy);
    const float wx = gx - x0f;
    const float wy = gy - y0f;
    const int x0 = (int)x0f;
    const int y0 = (int)y0f;

    const float4 g = __ldg((const float4*)(grad_out + (size_t)p * C_DIM + quad * 4));

    const bool vx0 = ((unsigned)x0 < (unsigned)W_DIM);
    const bool vx1 = ((unsigned)(x0 + 1) < (unsigned)W_DIM);
    const bool vy0 = ((unsigned)y0 < (unsigned)H_DIM);
    const bool vy1 = ((unsigned)(y0 + 1) < (unsigned)H_DIM);

    const float w00 = (1.0f - wy) * (1.0f - wx);
    const float w01 = (1.0f - wy) * wx;
    const float w10 = wy * (1.0f - wx);
    const float w11 = wy * wx;

    const int dy0 = (y0 - y) * W_DIM;
    const int dy1 = dy0 + W_DIM;
    const int dx0 = x0 - x;
    float* outq = out + (size_t)p * C_DIM + quad * 4;

    if (vy0 & vx0) {
        float4 v = make_float4(g.x * w00, g.y * w00, g.z * w00, g.w * w00);
        atomicAdd((float4*)(outq + (long long)(dy0 + dx0) * C_DIM), v);
    }
    if (vy0 & vx1) {
        float4 v = make_float4(g.x * w01, g.y * w01, g.z * w01, g.w * w01);
        atomicAdd((float4*)(outq + (long long)(dy0 + dx0 + 1) * C_DIM), v);
    }
    if (vy1 & vx0) {
        float4 v = make_float4(g.x * w10, g.y * w10, g.z * w10, g.w * w10);
        atomicAdd((float4*)(outq + (long long)(dy1 + dx0) * C_DIM), v);
    }
    if (vy1 & vx1) {
        float4 v = make_float4(g.x * w11, g.y * w11, g.z * w11, g.w * w11);
        atomicAdd((float4*)(outq + (long long)(dy1 + dx0 + 1) * C_DIM), v);
    }
}

extern "C" void kernel_launch(void* const* d_in, const int* in_sizes, int n_in,
                              void* d_out, int out_size) {
    const float* grad_out = (const float*)d_in[0];
    const float* u        = (const float*)d_in[1];
    float* out = (float*)d_out;

    const int B = in_sizes[1] / (H_DIM * W_DIM * 2);
    const int total_quads = B * H_DIM * W_DIM * 4;    // exact multiple of 256

    const int n4 = out_size / 4;                      // float4 count
    zero_out<<<8192, 256>>>((float4*)out, n4);

    warp_transpose_scatter<<<total_quads / 256, 256>>>(grad_out, u, out);
}

// round 10
// speedup vs baseline: 1.6382x; 1.0030x over previous
#include <cuda_runtime.h>
#include <cuda_bf16.h>
#include <math.h>

// WarpTranspose: adjoint of bilinear warp (flow-guided bilinear scatter-add).
// grad_out: [B,H,W,C] f32, u: [B,H,W,2] f32 (dx,dy), out: [B,H,W,C] f32.
//
// Structure: zero kernel -> scatter kernel, linked with Programmatic Dependent
// Launch. The scatter sits at the per-SM RED lane-op floor (16 lane-ops/px x
// ~0.854 cyc = ~95us); PDL hides the zero kernel's tail and the launch gap by
// letting scatter blocks start and issue their independent loads (u, grad_out)
// before synchronizing on the zero kernel's completion.

#define H_DIM 512
#define W_DIM 512
#define C_DIM 16

// ---------------- zero kernel: 134MB of float4 stores at DRAM speed --------
__global__ void __launch_bounds__(256)
zero_out(float4* __restrict__ out4, int n4) {
    const int stride = gridDim.x * 256;
    const float4 z = make_float4(0.f, 0.f, 0.f, 0.f);
    #pragma unroll 4
    for (int i = blockIdx.x * 256 + threadIdx.x; i < n4; i += stride)
        out4[i] = z;
    // allow the dependent scatter grid to begin launching as we retire
    cudaTriggerProgrammaticLaunchCompletion();
}

// ---------------- scatter: R1 mapping (best known, at RED floor) -----------
__global__ void __launch_bounds__(256)
warp_transpose_scatter(const float* __restrict__ grad_out,
                       const float* __restrict__ u,
                       float* __restrict__ out) {
    const int gid = blockIdx.x * 256 + threadIdx.x;   // grid is exact: no guard

    const int quad = gid & 3;      // which float4 of the 16 channels
    const int p    = gid >> 2;     // pixel index: ((b*H + y)*W + x)

    const int x = p & (W_DIM - 1);
    const int y = (p >> 9) & (H_DIM - 1);

    // independent loads — issued BEFORE the PDL grid sync so they overlap the
    // zero kernel's tail
    const float2 uv = __ldg((const float2*)(u + 2 * (size_t)p));
    const float4 g  = __ldg((const float4*)(grad_out + (size_t)p * C_DIM + quad * 4));

    const float gx = (float)x + uv.x;
    const float gy = (float)y + uv.y;

    const float x0f = floorf(gx);
    const float y0f = floorf(gy);
    const float wx = gx - x0f;
    const float wy = gy - y0f;
    const int x0 = (int)x0f;
    const int y0 = (int)y0f;

    const bool vx0 = ((unsigned)x0 < (unsigned)W_DIM);
    const bool vx1 = ((unsigned)(x0 + 1) < (unsigned)W_DIM);
    const bool vy0 = ((unsigned)y0 < (unsigned)H_DIM);
    const bool vy1 = ((unsigned)(y0 + 1) < (unsigned)H_DIM);

    const float w00 = (1.0f - wy) * (1.0f - wx);
    const float w01 = (1.0f - wy) * wx;
    const float w10 = wy * (1.0f - wx);
    const float w11 = wy * wx;

    const int dy0 = (y0 - y) * W_DIM;
    const int dy1 = dy0 + W_DIM;
    const int dx0 = x0 - x;
    float* outq = out + (size_t)p * C_DIM + quad * 4;

    // wait until the zero kernel's stores are visible, then RMW
    cudaGridDependencySynchronize();

    if (vy0 & vx0) {
        float4 v = make_float4(g.x * w00, g.y * w00, g.z * w00, g.w * w00);
        atomicAdd((float4*)(outq + (long long)(dy0 + dx0) * C_DIM), v);
    }
    if (vy0 & vx1) {
        float4 v = make_float4(g.x * w01, g.y * w01, g.z * w01, g.w * w01);
        atomicAdd((float4*)(outq + (long long)(dy0 + dx0 + 1) * C_DIM), v);
    }
    if (vy1 & vx0) {
        float4 v = make_float4(g.x * w10, g.y * w10, g.z * w10, g.w * w10);
        atomicAdd((float4*)(outq + (long long)(dy1 + dx0) * C_DIM), v);
    }
    if (vy1 & vx1) {
        float4 v = make_float4(g.x * w11, g.y * w11, g.z * w11, g.w * w11);
        atomicAdd((float4*)(outq + (long long)(dy1 + dx0 + 1) * C_DIM), v);
    }
}

extern "C" void kernel_launch(void* const* d_in, const int* in_sizes, int n_in,
                              void* d_out, int out_size) {
    const float* grad_out = (const float*)d_in[0];
    const float* u        = (const float*)d_in[1];
    float* out = (float*)d_out;

    const int B = in_sizes[1] / (H_DIM * W_DIM * 2);
    const int total_quads = B * H_DIM * W_DIM * 4;    // exact multiple of 256

    const int n4 = out_size / 4;                      // float4 count
    zero_out<<<8192, 256>>>((float4*)out, n4);

    // scatter with Programmatic Stream Serialization (PDL)
    cudaLaunchConfig_t cfg = {};
    cfg.gridDim = dim3(total_quads / 256);
    cfg.blockDim = dim3(256);
    cfg.dynamicSmemBytes = 0;
    cfg.stream = 0;
    cudaLaunchAttribute attrs[1];
    attrs[0].id = cudaLaunchAttributeProgrammaticStreamSerialization;
    attrs[0].val.programmaticStreamSerializationAllowed = 1;
    cfg.attrs = attrs;
    cfg.numAttrs = 1;
    cudaLaunchKernelEx(&cfg, warp_transpose_scatter, grad_out, u, out);
}

// round 13
// speedup vs baseline: 1.6892x; 1.0311x over previous
#include <cuda_runtime.h>
#include <cuda_bf16.h>
#include <math.h>

// WarpTranspose: adjoint of bilinear warp (flow-guided bilinear scatter-add).
// grad_out: [B,H,W,C] f32, u: [B,H,W,2] f32 (dx,dy), out: [B,H,W,C] f32.
//
// Structure: zero kernel (descending order, L2::evict_last stores) -> PDL ->
// scatter (R1 mapping: 4 thr/px, 4x 64B-aligned float4 REDs, streaming inputs
// loaded with L2::evict_first). Goal: keep the output tensor L2-resident so
// the atomic RMWs hit L2 instead of round-tripping DRAM.

#define H_DIM 512
#define W_DIM 512
#define C_DIM 16

// ---------------- zero kernel ------------------------------------------------
__global__ void __launch_bounds__(256)
zero_out(float4* __restrict__ out4, int n4) {
    unsigned long long pol_last;
    asm("createpolicy.fractional.L2::evict_last.b64 %0, 1.0;" : "=l"(pol_last));

    const int stride = gridDim.x * 256;
    // descending: the last-zeroed (freshest in L2) lines are the low addresses,
    // which the scatter kernel touches first.
    #pragma unroll 4
    for (int i = blockIdx.x * 256 + threadIdx.x; i < n4; i += stride) {
        float4* p = out4 + (n4 - 1 - i);
        asm volatile("st.global.L2::cache_hint.v4.f32 [%0], {%1, %2, %3, %4}, %5;"
                     :: "l"(p), "f"(0.f), "f"(0.f), "f"(0.f), "f"(0.f),
                        "l"(pol_last) : "memory");
    }
    cudaTriggerProgrammaticLaunchCompletion();
}

// ---------------- scatter ----------------------------------------------------
__global__ void __launch_bounds__(256)
warp_transpose_scatter(const float* __restrict__ grad_out,
                       const float* __restrict__ u,
                       float* __restrict__ out) {
    unsigned long long pol_first;
    asm("createpolicy.fractional.L2::evict_first.b64 %0, 1.0;" : "=l"(pol_first));

    const int gid = blockIdx.x * 256 + threadIdx.x;   // grid is exact: no guard

    const int quad = gid & 3;      // which float4 of the 16 channels
    const int p    = gid >> 2;     // pixel index: ((b*H + y)*W + x)

    const int x = p & (W_DIM - 1);
    const int y = (p >> 9) & (H_DIM - 1);

    // streaming loads, evict_first so they don't displace output lines.
    // Issued before the PDL grid sync to overlap the zero kernel's tail.
    float ux, uy;
    asm volatile("ld.global.nc.L2::cache_hint.v2.f32 {%0, %1}, [%2], %3;"
                 : "=f"(ux), "=f"(uy)
                 : "l"(u + 2 * (size_t)p), "l"(pol_first));
    float4 g;
    asm volatile("ld.global.nc.L2::cache_hint.v4.f32 {%0, %1, %2, %3}, [%4], %5;"
                 : "=f"(g.x), "=f"(g.y), "=f"(g.z), "=f"(g.w)
                 : "l"(grad_out + (size_t)p * C_DIM + quad * 4), "l"(pol_first));

    const float gx = (float)x + ux;
    const float gy = (float)y + uy;

    const float x0f = floorf(gx);
    const float y0f = floorf(gy);
    const float wx = gx - x0f;
    const float wy = gy - y0f;
    const int x0 = (int)x0f;
    const int y0 = (int)y0f;

    const bool vx0 = ((unsigned)x0 < (unsigned)W_DIM);
    const bool vx1 = ((unsigned)(x0 + 1) < (unsigned)W_DIM);
    const bool vy0 = ((unsigned)y0 < (unsigned)H_DIM);
    const bool vy1 = ((unsigned)(y0 + 1) < (unsigned)H_DIM);

    const float w00 = (1.0f - wy) * (1.0f - wx);
    const float w01 = (1.0f - wy) * wx;
    const float w10 = wy * (1.0f - wx);
    const float w11 = wy * wx;

    const int dy0 = (y0 - y) * W_DIM;
    const int dy1 = dy0 + W_DIM;
    const int dx0 = x0 - x;
    float* outq = out + (size_t)p * C_DIM + quad * 4;

    // wait until the zero kernel's stores are visible, then RMW
    cudaGridDependencySynchronize();

    if (vy0 & vx0) {
        float4 v = make_float4(g.x * w00, g.y * w00, g.z * w00, g.w * w00);
        atomicAdd((float4*)(outq + (long long)(dy0 + dx0) * C_DIM), v);
    }
    if (vy0 & vx1) {
        float4 v = make_float4(g.x * w01, g.y * w01, g.z * w01, g.w * w01);
        atomicAdd((float4*)(outq + (long long)(dy0 + dx0 + 1) * C_DIM), v);
    }
    if (vy1 & vx0) {
        float4 v = make_float4(g.x * w10, g.y * w10, g.z * w10, g.w * w10);
        atomicAdd((float4*)(outq + (long long)(dy1 + dx0) * C_DIM), v);
    }
    if (vy1 & vx1) {
        float4 v = make_float4(g.x * w11, g.y * w11, g.z * w11, g.w * w11);
        atomicAdd((float4*)(outq + (long long)(dy1 + dx0 + 1) * C_DIM), v);
    }
}

extern "C" void kernel_launch(void* const* d_in, const int* in_sizes, int n_in,
                              void* d_out, int out_size) {
    const float* grad_out = (const float*)d_in[0];
    const float* u        = (const float*)d_in[1];
    float* out = (float*)d_out;

    const int B = in_sizes[1] / (H_DIM * W_DIM * 2);
    const int total_quads = B * H_DIM * W_DIM * 4;    // exact multiple of 256

    const int n4 = out_size / 4;                      // float4 count
    zero_out<<<8192, 256>>>((float4*)out, n4);

    // scatter with Programmatic Stream Serialization (PDL)
    cudaLaunchConfig_t cfg = {};
    cfg.gridDim = dim3(total_quads / 256);
    cfg.blockDim = dim3(256);
    cfg.dynamicSmemBytes = 0;
    cfg.stream = 0;
    cudaLaunchAttribute attrs[1];
    attrs[0].id = cudaLaunchAttributeProgrammaticStreamSerialization;
    attrs[0].val.programmaticStreamSerializationAllowed = 1;
    cfg.attrs = attrs;
    cfg.numAttrs = 1;
    cudaLaunchKernelEx(&cfg, warp_transpose_scatter, grad_out, u, out);
}